// round 4
// baseline (speedup 1.0000x reference)
#include <cuda_runtime.h>
#include <math.h>

// Problem constants
#define LSEQ 700
#define BATCH 32
#define DIN 41
#define HID 800
#define GATES 3200          // 4*HID
#define H2 1600             // 2*HID
#define NCOORD 2100         // 3*LSEQ

// ---------------- device scratch (allocation-free rule: __device__ globals) ---
__device__ float g_G0[2L * LSEQ * GATES * BATCH];   // [2][700][3200][32]
__device__ float g_G1[2L * LSEQ * GATES * BATCH];
__device__ float g_h0[LSEQ * H2 * BATCH];           // [700][1600][32]
__device__ float g_h1[LSEQ * H2 * BATCH];
__device__ float g_ang[LSEQ * BATCH * 3];
__device__ unsigned g_cnt[4];                       // barrier counters [layer*2+dir]
__device__ unsigned g_ack[4];

// ---------------- packed fp32x2 helpers (R2/R3 proved bit-identical to scalar)
__device__ __forceinline__ void ffma2(unsigned long long& d,
                                      unsigned long long a,
                                      unsigned long long b)
{
    asm("fma.rn.f32x2 %0, %1, %2, %3;" : "=l"(d) : "l"(a), "l"(b), "l"(d));
}
__device__ __forceinline__ unsigned long long dupf(float x)
{
    unsigned long long r;
    asm("mov.b64 %0, {%1, %1};" : "=l"(r) : "f"(x));
    return r;
}
__device__ __forceinline__ unsigned long long packf(float x, float y)
{
    unsigned long long r;
    asm("mov.b64 %0, {%1, %2};" : "=l"(r) : "f"(x), "f"(y));
    return r;
}
__device__ __forceinline__ float2 unpackf(unsigned long long u)
{
    float2 f;
    asm("mov.b64 {%0, %1}, %2;" : "=f"(f.x), "=f"(f.y) : "l"(u));
    return f;
}
__device__ __forceinline__ float sigf(float x) { return 1.f / (1.f + expf(-x)); }

// =============================================================================
// Tiled fp32 GEMM (f32x2 inner product) producing gate pre-activations
// G[dir][t][j][b].  C[row=(t,b)][col=(dir,j)] = sum_k A[row][k]*B[col][k]+biases
// amode 0: A[row][k] = x[b][t][k]      (layer0, K=41)
// amode 1: A[row][k] = h0[t][k][b]     (layer1, K=1600)
// M = 22400 (175*128), N = 6400 (50*128); K masked.
// =============================================================================
__global__ __launch_bounds__(256, 2)
void gemm_gates(const float* __restrict__ A, const float* __restrict__ B,
                const float* __restrict__ bias1, const float* __restrict__ bias2,
                float* __restrict__ Gout, int K, int ldb, int amode)
{
    __shared__ float As[16][128];
    __shared__ float Bs[16][128];
    int tid  = threadIdx.x;
    int row0 = blockIdx.y * 128;
    int col0 = blockIdx.x * 128;
    int tx = tid & 15, ty = tid >> 4;

    unsigned long long acc2[8][4];
#pragma unroll
    for (int m = 0; m < 8; m++)
#pragma unroll
        for (int n = 0; n < 4; n++) acc2[m][n] = 0ull;   // two packed +0.0f

    for (int kt = 0; kt < K; kt += 16) {
#pragma unroll
        for (int ii = 0; ii < 8; ii++) {
            int i = tid + 256 * ii;
            int kk = i >> 7, r = i & 127;
            int row = row0 + r;
            int k = kt + kk;
            float v = 0.f;
            if (k < K) {
                if (amode == 0) v = A[(row & 31) * (LSEQ * DIN) + (row >> 5) * DIN + k];
                else            v = A[(row >> 5) * (H2 * BATCH) + k * BATCH + (row & 31)];
            }
            As[kk][r] = v;
        }
#pragma unroll
        for (int ii = 0; ii < 8; ii++) {
            int i = tid + 256 * ii;
            int c = i >> 4, kk = i & 15;
            int k = kt + kk;
            Bs[kk][c] = (k < K) ? B[(col0 + c) * ldb + k] : 0.f;
        }
        __syncthreads();
#pragma unroll
        for (int kk = 0; kk < 16; kk++) {
            float a[8];
            *(float4*)&a[0] = *(const float4*)&As[kk][ty * 8];
            *(float4*)&a[4] = *(const float4*)&As[kk][ty * 8 + 4];
            ulonglong2 b01 = *(const ulonglong2*)&Bs[kk][tx * 8];
            ulonglong2 b23 = *(const ulonglong2*)&Bs[kk][tx * 8 + 4];
            unsigned long long bp[4] = { b01.x, b01.y, b23.x, b23.y };
#pragma unroll
            for (int m = 0; m < 8; m++) {
                unsigned long long am = dupf(a[m]);
#pragma unroll
                for (int n = 0; n < 4; n++) ffma2(acc2[m][n], am, bp[n]);
            }
        }
        __syncthreads();
    }

#pragma unroll
    for (int m = 0; m < 8; m++) {
        int row = row0 + ty * 8 + m;
        int t = row >> 5, b = row & 31;
#pragma unroll
        for (int n = 0; n < 4; n++) {
            float2 v = unpackf(acc2[m][n]);
            int c0 = col0 + tx * 8 + 2 * n;
#pragma unroll
            for (int q = 0; q < 2; q++) {
                int col = c0 + q;
                int dir = (col >= GATES) ? 1 : 0;
                int j = col - dir * GATES;
                float val = (q == 0 ? v.x : v.y) + bias1[col] + bias2[col];
                Gout[((dir * LSEQ + t) * GATES + j) * BATCH + b] = val;
            }
        }
    }
}

// =============================================================================
// Persistent bidirectional LSTM recurrence for one layer. ONE launch per layer.
// Grid 100 CTAs x 256 threads. CTA c: dir = c/50, owns 16 units (8 packed
// pairs). Whh slice cached in smem (float2 unit-pairs, 204.8KB). h streamed
// through smem in 80-k chunks via __ldcg. Cell state in registers.
// Software grid barrier per direction (50 CTAs) with ack-based reset so the
// kernel is replay-deterministic.
// =============================================================================
#define RBK 80
#define NCTA_DIR 50
#define SMEM_LSTM (8 * 4 * HID * 8 + RBK * 32 * 4)   // 204800 + 10240 bytes

__global__ __launch_bounds__(256, 1)
void lstm_persist(const float* __restrict__ Whh, int layer)
{
    extern __shared__ char smem[];
    float2* ws = (float2*)smem;                       // [8 pairs][4 gates][800]
    float*  hs = (float*)(smem + 8 * 4 * HID * 8);    // [RBK][32]

    const float* G = layer ? g_G1 : g_G0;
    float* hout    = layer ? g_h1 : g_h0;

    int c   = blockIdx.x;
    int dir = c / NCTA_DIR;
    int ubase = (c % NCTA_DIR) * 16;
    int tid = threadIdx.x;
    int b = tid & 31, ul = tid >> 5;                  // batch lane, pair slot
    int u0 = ubase + 2 * ul;

    unsigned* cnt = &g_cnt[layer * 2 + dir];
    unsigned* ack = &g_ack[layer * 2 + dir];

    // ---- load & pack Whh slice into smem (once) ----
    // ws[(p*4+g)*800 + k] = (W[g*800+ubase+2p][k], W[g*800+ubase+2p+1][k])
    const float* Wd = Whh + (long)dir * GATES * HID;
    for (int i = tid; i < 8 * 4 * HID; i += 256) {
        int k = i % HID;
        int pg = i / HID;            // p*4+g
        int p = pg >> 2, g = pg & 3;
        int urow0 = g * HID + ubase + 2 * p;
        ws[i] = make_float2(Wd[(long)urow0 * HID + k], Wd[(long)(urow0 + 1) * HID + k]);
    }
    __syncthreads();

    float c0r = 0.f, c1r = 0.f;      // cell state (registers, persistent)

    for (int s = 0; s < LSEQ; s++) {
        int t = dir ? (LSEQ - 1 - s) : s;

        // gate pre-activations from G
        long gb = ((long)(dir * LSEQ + t)) * GATES * BATCH;
        unsigned long long acc[4];
#pragma unroll
        for (int g = 0; g < 4; g++) {
            float v0 = G[gb + (long)(g * HID + u0) * BATCH + b];
            float v1 = G[gb + (long)(g * HID + u0 + 1) * BATCH + b];
            acc[g] = packf(v0, v1);
        }

        if (s > 0) {
            int tp = dir ? t + 1 : t - 1;
            const float* hp = hout + ((long)tp * H2 + dir * HID) * BATCH;
            for (int k0 = 0; k0 < HID; k0 += RBK) {
                __syncthreads();
#pragma unroll
                for (int i = 0; i < (RBK * 32) / 256; i++)
                    hs[tid + 256 * i] = __ldcg(hp + k0 * 32 + tid + 256 * i);
                __syncthreads();
#pragma unroll 4
                for (int k = 0; k < RBK; k += 2) {
                    unsigned long long h0d = dupf(hs[k * 32 + b]);
                    unsigned long long h1d = dupf(hs[k * 32 + 32 + b]);
#pragma unroll
                    for (int g = 0; g < 4; g++) {
                        ulonglong2 w2 = *(const ulonglong2*)(ws + (ul * 4 + g) * HID + k0 + k);
                        ffma2(acc[g], w2.x, h0d);
                        ffma2(acc[g], w2.y, h1d);
                    }
                }
            }
        }

        // LSTM cell (two units)
        float2 ai = unpackf(acc[0]);
        float2 af = unpackf(acc[1]);
        float2 ag = unpackf(acc[2]);
        float2 ao = unpackf(acc[3]);

        c0r = sigf(af.x) * c0r + sigf(ai.x) * tanhf(ag.x);
        c1r = sigf(af.y) * c1r + sigf(ai.y) * tanhf(ag.y);
        float h0v = sigf(ao.x) * tanhf(c0r);
        float h1v = sigf(ao.y) * tanhf(c1r);

        long hix = ((long)t * H2 + dir * HID + u0) * BATCH + b;
        __stcg(hout + hix, h0v);
        __stcg(hout + hix + BATCH, h1v);

        // ---- grid barrier over this direction's 50 CTAs ----
        __syncthreads();
        if (tid == 0) {
            asm volatile("red.release.gpu.global.add.u32 [%0], %1;"
                         :: "l"(cnt), "r"(1u) : "memory");
            unsigned target = (unsigned)(s + 1) * NCTA_DIR;
            unsigned v;
            do {
                asm volatile("ld.acquire.gpu.global.u32 %0, [%1];"
                             : "=r"(v) : "l"(cnt) : "memory");
            } while (v < target);
        }
        __syncthreads();
    }

    // ---- replay-safe counter reset via ack ----
    if (tid == 0) {
        asm volatile("red.release.gpu.global.add.u32 [%0], %1;"
                     :: "l"(ack), "r"(1u) : "memory");
        if ((c % NCTA_DIR) == 0) {
            unsigned v;
            do {
                asm volatile("ld.acquire.gpu.global.u32 %0, [%1];"
                             : "=r"(v) : "l"(ack) : "memory");
            } while (v < NCTA_DIR);
            *cnt = 0;
            *ack = 0;
            __threadfence();
        }
    }
}

// =============================================================================
// Fused head: logits = h1 @ w_lin^T + b_lin; softmax over BATCH dim (axis=1,
// faithful to source); angles = atan2(p@sin(alpha), p@cos(alpha)).
// Grid 700, block 640 = 20 warps (warp j, lane b).
// FIX (R4): k-chunk = 160 (1600/160 = 10 exact). The old 128-chunk loop ran
// 13 iterations and read 64 features past H2 (next timestep's h1 + OOB w_lin),
// which was the sole source of the 1.086e-2 rel_err.
// =============================================================================
#define HCHUNK 160
__global__ __launch_bounds__(640)
void head_kernel(const float* __restrict__ wlin, const float* __restrict__ blin,
                 const float* __restrict__ alphabet)
{
    int l = blockIdx.x;
    int tid = threadIdx.x;
    int j = tid >> 5, b = tid & 31;

    __shared__ float hs[HCHUNK * 32];
    __shared__ float ps[20][32];
    __shared__ float sa[60], ca[60];

    if (tid < 60) { float v = alphabet[tid]; sa[tid] = sinf(v); ca[tid] = cosf(v); }

    float acc = blin[j];
    const float* hb = g_h1 + (long)l * (H2 * BATCH);
    const float* w = wlin + j * H2;
    for (int k0 = 0; k0 < H2; k0 += HCHUNK) {
        __syncthreads();
#pragma unroll
        for (int i = 0; i < (HCHUNK * 32) / 640; i++)
            hs[tid + 640 * i] = hb[k0 * 32 + tid + 640 * i];
        __syncthreads();
#pragma unroll 8
        for (int k = 0; k < HCHUNK; k += 4) {
            float4 w4 = *(const float4*)(w + k0 + k);
            acc += w4.x * hs[(k + 0) * 32 + b];
            acc += w4.y * hs[(k + 1) * 32 + b];
            acc += w4.z * hs[(k + 2) * 32 + b];
            acc += w4.w * hs[(k + 3) * 32 + b];
        }
    }
    // softmax over lanes (= batch dim, axis=1 faithful to source)
    float m = acc;
#pragma unroll
    for (int o = 16; o; o >>= 1) m = fmaxf(m, __shfl_xor_sync(0xffffffffu, m, o));
    float e = expf(acc - m);
    float ssum = e;
#pragma unroll
    for (int o = 16; o; o >>= 1) ssum += __shfl_xor_sync(0xffffffffu, ssum, o);
    ps[j][b] = e / ssum;
    __syncthreads();

    if (tid < 96) {
        int b2 = tid / 3, i = tid - b2 * 3;
        float ssin = 0.f, scos = 0.f;
#pragma unroll
        for (int jj = 0; jj < 20; jj++) {
            float p = ps[jj][b2];
            ssin += p * sa[jj * 3 + i];
            scos += p * ca[jj * 3 + i];
        }
        g_ang[l * 96 + b2 * 3 + i] = atan2f(ssin, scos);
    }
}

// =============================================================================
// NeRF backbone extension. 1 block, 32 threads (one per batch element).
// Replicates reference's ang.reshape(L*3, B): phis[s][b] = ang_flat[s*32+b].
// =============================================================================
__global__ void nerf_kernel(float* __restrict__ out)
{
    int b = threadIdx.x;
    float ax = 0.f,   ay = 0.f,   az = 0.f;
    float bx = 100.f, by = 0.f,   bz = 0.f;
    float cx = 200.f, cy = 100.f, cz = 0.f;

    const float BL0 = 145.801f, BL1 = 152.326f, BL2 = 132.868f;
    const float TH0 = 2.124f,   TH1 = 1.941f,   TH2 = 2.028f;
    float d0a = -BL0 * cosf(TH0), d1a = BL0 * sinf(TH0);
    float d0b = -BL1 * cosf(TH1), d1b = BL1 * sinf(TH1);
    float d0c = -BL2 * cosf(TH2), d1c = BL2 * sinf(TH2);

    for (int s = 0; s < NCOORD; s++) {
        float phi = g_ang[s * 32 + b];
        int m = s - (s / 3) * 3;
        float d0 = (m == 0) ? d0a : (m == 1) ? d0b : d0c;
        float rs = (m == 0) ? d1a : (m == 1) ? d1b : d1c;

        float vx = cx - bx, vy = cy - by, vz = cz - bz;
        float inv = 1.f / (sqrtf(vx * vx + vy * vy + vz * vz) + 1e-12f);
        float bcx = vx * inv, bcy = vy * inv, bcz = vz * inv;

        float ux = bx - ax, uy = by - ay, uz = bz - az;
        float nx = uy * bcz - uz * bcy;
        float ny = uz * bcx - ux * bcz;
        float nz = ux * bcy - uy * bcx;
        float invn = 1.f / (sqrtf(nx * nx + ny * ny + nz * nz) + 1e-12f);
        nx *= invn; ny *= invn; nz *= invn;

        float mx = ny * bcz - nz * bcy;
        float my = nz * bcx - nx * bcz;
        float mz = nx * bcy - ny * bcx;

        float sp, cp;
        sincosf(phi, &sp, &cp);
        float d1 = rs * cp, d2 = rs * sp;

        float dx = cx + d0 * bcx + d1 * mx + d2 * nx;
        float dy = cy + d0 * bcy + d1 * my + d2 * ny;
        float dz = cz + d0 * bcz + d1 * mz + d2 * nz;

        out[s * 96 + b * 3 + 0] = dx;
        out[s * 96 + b * 3 + 1] = dy;
        out[s * 96 + b * 3 + 2] = dz;

        ax = bx; ay = by; az = bz;
        bx = cx; by = cy; bz = cz;
        cx = dx; cy = dy; cz = dz;
    }
}

// =============================================================================
extern "C" void kernel_launch(void* const* d_in, const int* in_sizes, int n_in,
                              void* d_out, int out_size)
{
    const float* x     = (const float*)d_in[0];
    const float* wih0  = (const float*)d_in[1];
    const float* whh0  = (const float*)d_in[2];
    const float* bih0  = (const float*)d_in[3];
    const float* bhh0  = (const float*)d_in[4];
    const float* wih1  = (const float*)d_in[5];
    const float* whh1  = (const float*)d_in[6];
    const float* bih1  = (const float*)d_in[7];
    const float* bhh1  = (const float*)d_in[8];
    const float* wlin  = (const float*)d_in[9];
    const float* blin  = (const float*)d_in[10];
    const float* alpha = (const float*)d_in[11];
    float* out = (float*)d_out;

    static int attr_done = 0;
    if (!attr_done) {
        cudaFuncSetAttribute(lstm_persist,
                             cudaFuncAttributeMaxDynamicSharedMemorySize, SMEM_LSTM);
        attr_done = 1;
    }

    dim3 gemm_grid(50, 175);   // N/128, M/128

    float* G0p; cudaGetSymbolAddress((void**)&G0p, g_G0);
    float* G1p; cudaGetSymbolAddress((void**)&G1p, g_G1);
    float* h0p; cudaGetSymbolAddress((void**)&h0p, g_h0);

    // Layer 0 input-side pre-activations: G0 = x @ Wih0^T + bih0 + bhh0
    gemm_gates<<<gemm_grid, 256>>>(x, wih0, bih0, bhh0, G0p, DIN, DIN, 0);

    // Layer 0 recurrence: single persistent launch (both directions)
    lstm_persist<<<100, 256, SMEM_LSTM>>>(whh0, 0);

    // Layer 1 input-side pre-activations: G1 = h0 @ Wih1^T + bih1 + bhh1
    gemm_gates<<<gemm_grid, 256>>>(h0p, wih1, bih1, bhh1, G1p, H2, H2, 1);

    // Layer 1 recurrence
    lstm_persist<<<100, 256, SMEM_LSTM>>>(whh1, 1);

    // Head: linear -> softmax(batch dim) -> angles
    head_kernel<<<LSEQ, 640>>>(wlin, blin, alpha);

    // NeRF extension -> output coords [2100][32][3]
    nerf_kernel<<<1, 32>>>(out);
}

// round 5
// speedup vs baseline: 1.0271x; 1.0271x over previous
#include <cuda_runtime.h>
#include <math.h>

// Problem constants
#define LSEQ 700
#define BATCH 32
#define DIN 41
#define HID 800
#define GATES 3200          // 4*HID
#define H2 1600             // 2*HID
#define NCOORD 2100         // 3*LSEQ

// ---------------- device scratch (allocation-free rule: __device__ globals) ---
__device__ float g_G0[2L * LSEQ * GATES * BATCH];   // [2][700][3200][32]
__device__ float g_G1[2L * LSEQ * GATES * BATCH];
__device__ float g_h0[LSEQ * H2 * BATCH];           // [700][1600][32]
__device__ float g_h1[LSEQ * H2 * BATCH];
__device__ float g_ang[LSEQ * BATCH * 3];
__device__ unsigned g_cnt[4];                       // barrier counters [layer*2+dir]
__device__ unsigned g_ack[4];

// ---------------- packed fp32x2 helpers (R2/R3 proved bit-identical to scalar)
__device__ __forceinline__ void ffma2(unsigned long long& d,
                                      unsigned long long a,
                                      unsigned long long b)
{
    asm("fma.rn.f32x2 %0, %1, %2, %3;" : "=l"(d) : "l"(a), "l"(b), "l"(d));
}
__device__ __forceinline__ unsigned long long dupf(float x)
{
    unsigned long long r;
    asm("mov.b64 %0, {%1, %1};" : "=l"(r) : "f"(x));
    return r;
}
__device__ __forceinline__ float2 unpackf(unsigned long long u)
{
    float2 f;
    asm("mov.b64 {%0, %1}, %2;" : "=f"(f.x), "=f"(f.y) : "l"(u));
    return f;
}
__device__ __forceinline__ float sigf(float x) { return 1.f / (1.f + expf(-x)); }

// =============================================================================
// Tiled fp32 GEMM (f32x2 inner product) producing gate pre-activations
// G[dir][t][j][b].  (unchanged from passing R4 kernel)
// =============================================================================
__global__ __launch_bounds__(256, 2)
void gemm_gates(const float* __restrict__ A, const float* __restrict__ B,
                const float* __restrict__ bias1, const float* __restrict__ bias2,
                float* __restrict__ Gout, int K, int ldb, int amode)
{
    __shared__ float As[16][128];
    __shared__ float Bs[16][128];
    int tid  = threadIdx.x;
    int row0 = blockIdx.y * 128;
    int col0 = blockIdx.x * 128;
    int tx = tid & 15, ty = tid >> 4;

    unsigned long long acc2[8][4];
#pragma unroll
    for (int m = 0; m < 8; m++)
#pragma unroll
        for (int n = 0; n < 4; n++) acc2[m][n] = 0ull;

    for (int kt = 0; kt < K; kt += 16) {
#pragma unroll
        for (int ii = 0; ii < 8; ii++) {
            int i = tid + 256 * ii;
            int kk = i >> 7, r = i & 127;
            int row = row0 + r;
            int k = kt + kk;
            float v = 0.f;
            if (k < K) {
                if (amode == 0) v = A[(row & 31) * (LSEQ * DIN) + (row >> 5) * DIN + k];
                else            v = A[(row >> 5) * (H2 * BATCH) + k * BATCH + (row & 31)];
            }
            As[kk][r] = v;
        }
#pragma unroll
        for (int ii = 0; ii < 8; ii++) {
            int i = tid + 256 * ii;
            int c = i >> 4, kk = i & 15;
            int k = kt + kk;
            Bs[kk][c] = (k < K) ? B[(col0 + c) * ldb + k] : 0.f;
        }
        __syncthreads();
#pragma unroll
        for (int kk = 0; kk < 16; kk++) {
            float a[8];
            *(float4*)&a[0] = *(const float4*)&As[kk][ty * 8];
            *(float4*)&a[4] = *(const float4*)&As[kk][ty * 8 + 4];
            ulonglong2 b01 = *(const ulonglong2*)&Bs[kk][tx * 8];
            ulonglong2 b23 = *(const ulonglong2*)&Bs[kk][tx * 8 + 4];
            unsigned long long bp[4] = { b01.x, b01.y, b23.x, b23.y };
#pragma unroll
            for (int m = 0; m < 8; m++) {
                unsigned long long am = dupf(a[m]);
#pragma unroll
                for (int n = 0; n < 4; n++) ffma2(acc2[m][n], am, bp[n]);
            }
        }
        __syncthreads();
    }

#pragma unroll
    for (int m = 0; m < 8; m++) {
        int row = row0 + ty * 8 + m;
        int t = row >> 5, b = row & 31;
#pragma unroll
        for (int n = 0; n < 4; n++) {
            float2 v = unpackf(acc2[m][n]);
            int c0 = col0 + tx * 8 + 2 * n;
#pragma unroll
            for (int q = 0; q < 2; q++) {
                int col = c0 + q;
                int dir = (col >= GATES) ? 1 : 0;
                int j = col - dir * GATES;
                float val = (q == 0 ? v.x : v.y) + bias1[col] + bias2[col];
                Gout[((dir * LSEQ + t) * GATES + j) * BATCH + b] = val;
            }
        }
    }
}

// =============================================================================
// Persistent bidirectional LSTM recurrence, register-tiled dot phase.
// Grid 100 CTAs x 256 threads; CTA c: dir=c/50, units ubase..ubase+15.
// Per step: C[64 gate-rows][32 batch] = Wslice[64][800] x h[800][32].
// Dot mapping: tid = g*64 + u2*8 + p2  (g=gate, u2=unit-pair, p2=batch-quad).
//   per k: LDS.64 (2 weights) + LDS.128 (2 h-pairs) + 4 FFMA2. Full K per
//   thread -> no cross-thread reduction. Weights resident in smem, stride-68
//   padded (conflict-free reads). Gate partials combined via 8KB smem buffer
//   (overlaps h staging), then cell update on (unit,pair) mapping with
//   register-resident cell state.
// =============================================================================
#define NCTA_DIR 50
#define WSPAD 68
#define HCH 100
#define SMEM_LSTM (HID * WSPAD * 4 + HCH * 32 * 4)   // 217600 + 12800 = 230400

__global__ __launch_bounds__(256, 1)
void lstm_persist(const float* __restrict__ Whh, int layer)
{
    extern __shared__ char smem[];
    float*  ws = (float*)smem;                         // [800][WSPAD] (64 rows used)
    float*  hs = (float*)(smem + HID * WSPAD * 4);     // [HCH][32], reused as pb
    float2* pb = (float2*)hs;                          // [64 rows][16 pairs]

    const float* G = layer ? g_G1 : g_G0;
    float* hout    = layer ? g_h1 : g_h0;

    int c   = blockIdx.x;
    int dir = c / NCTA_DIR;
    int ubase = (c % NCTA_DIR) * 16;
    int tid = threadIdx.x;

    // dot-phase mapping
    int g  = tid >> 6;          // gate 0..3
    int u2 = (tid >> 3) & 7;    // unit pair-group: units 2*u2, 2*u2+1
    int p2 = tid & 7;           // batch quad: batches 4*p2 .. 4*p2+3
    // cell-phase mapping
    int cu = tid >> 4;          // unit 0..15
    int cp = tid & 15;          // batch pair 0..15

    unsigned* cnt = &g_cnt[layer * 2 + dir];
    unsigned* ack = &g_ack[layer * 2 + dir];

    // ---- load Whh slice into smem (once): ws[k][row], row = g*16 + u ----
    const float* Wd = Whh + (long)dir * GATES * HID;
    for (int i = tid; i < 64 * HID; i += 256) {
        int row = i / HID;           // 0..63  (gmem-coalesced over k)
        int k   = i % HID;
        int gg = row >> 4, uu = row & 15;
        ws[k * WSPAD + row] = Wd[(long)(gg * HID + ubase + uu) * HID + k];
    }
    __syncthreads();

    float c0r = 0.f, c1r = 0.f;      // cell state for (cu, batches 2cp, 2cp+1)

    for (int s = 0; s < LSEQ; s++) {
        int t = dir ? (LSEQ - 1 - s) : s;

        // prefetch G pre-activations (cell mapping) early: 4 gates x f32x2
        long gb = ((long)(dir * LSEQ + t)) * GATES * BATCH;
        float2 gpre[4];
#pragma unroll
        for (int gg = 0; gg < 4; gg++)
            gpre[gg] = *(const float2*)&G[gb + (long)(gg * HID + ubase + cu) * BATCH + 2 * cp];

        // ---- dot phase: acc[uu][pp] over full K ----
        unsigned long long acc00 = 0ull, acc01 = 0ull, acc10 = 0ull, acc11 = 0ull;

        if (s > 0) {
            int tp = dir ? t + 1 : t - 1;
            const float* hp = hout + ((long)tp * H2 + dir * HID) * BATCH;
            const float* wrow = ws + g * 16 + 2 * u2;
            for (int k0 = 0; k0 < HID; k0 += HCH) {
                __syncthreads();
                for (int i = tid; i < HCH * 32; i += 256)
                    hs[i] = __ldcg(hp + k0 * 32 + i);
                __syncthreads();
#pragma unroll 4
                for (int k = 0; k < HCH; k++) {
                    float2 w2 = *(const float2*)(wrow + (k0 + k) * WSPAD);
                    ulonglong2 h4 = *(const ulonglong2*)(hs + k * 32 + 4 * p2);
                    unsigned long long w0d = dupf(w2.x);
                    unsigned long long w1d = dupf(w2.y);
                    ffma2(acc00, w0d, h4.x);
                    ffma2(acc01, w0d, h4.y);
                    ffma2(acc10, w1d, h4.x);
                    ffma2(acc11, w1d, h4.y);
                }
            }
        }
        __syncthreads();   // hs reads done before pb overwrite

        // ---- publish gate partials: pb[row][pair] ----
        {
            int row0 = g * 16 + 2 * u2;
            float2* dst0 = pb + (long)row0 * 16 + 2 * p2;
            float2* dst1 = pb + (long)(row0 + 1) * 16 + 2 * p2;
            dst0[0] = unpackf(acc00);
            dst0[1] = unpackf(acc01);
            dst1[0] = unpackf(acc10);
            dst1[1] = unpackf(acc11);
        }
        __syncthreads();

        // ---- cell phase: thread (cu, cp) ----
        {
            float2 di = pb[(0 * 16 + cu) * 16 + cp];
            float2 df = pb[(1 * 16 + cu) * 16 + cp];
            float2 dg = pb[(2 * 16 + cu) * 16 + cp];
            float2 do_ = pb[(3 * 16 + cu) * 16 + cp];

            float ai0 = gpre[0].x + di.x, ai1 = gpre[0].y + di.y;
            float af0 = gpre[1].x + df.x, af1 = gpre[1].y + df.y;
            float ag0 = gpre[2].x + dg.x, ag1 = gpre[2].y + dg.y;
            float ao0 = gpre[3].x + do_.x, ao1 = gpre[3].y + do_.y;

            c0r = sigf(af0) * c0r + sigf(ai0) * tanhf(ag0);
            c1r = sigf(af1) * c1r + sigf(ai1) * tanhf(ag1);
            float h0v = sigf(ao0) * tanhf(c0r);
            float h1v = sigf(ao1) * tanhf(c1r);

            float2 hv = make_float2(h0v, h1v);
            __stcg((float2*)(hout + ((long)t * H2 + dir * HID + ubase + cu) * BATCH + 2 * cp), hv);
        }

        // ---- grid barrier over this direction's 50 CTAs ----
        __syncthreads();
        if (tid == 0) {
            asm volatile("red.release.gpu.global.add.u32 [%0], %1;"
                         :: "l"(cnt), "r"(1u) : "memory");
            unsigned target = (unsigned)(s + 1) * NCTA_DIR;
            unsigned v;
            do {
                asm volatile("ld.acquire.gpu.global.u32 %0, [%1];"
                             : "=r"(v) : "l"(cnt) : "memory");
            } while (v < target);
        }
        __syncthreads();
    }

    // ---- replay-safe counter reset via ack ----
    if (tid == 0) {
        asm volatile("red.release.gpu.global.add.u32 [%0], %1;"
                     :: "l"(ack), "r"(1u) : "memory");
        if ((c % NCTA_DIR) == 0) {
            unsigned v;
            do {
                asm volatile("ld.acquire.gpu.global.u32 %0, [%1];"
                             : "=r"(v) : "l"(ack) : "memory");
            } while (v < NCTA_DIR);
            *cnt = 0;
            *ack = 0;
            __threadfence();
        }
    }
}

// =============================================================================
// Fused head (k-chunk 160, fixed in R4): linear -> softmax over BATCH dim ->
// angles.  Grid 700, block 640.
// =============================================================================
#define HCHUNK 160
__global__ __launch_bounds__(640)
void head_kernel(const float* __restrict__ wlin, const float* __restrict__ blin,
                 const float* __restrict__ alphabet)
{
    int l = blockIdx.x;
    int tid = threadIdx.x;
    int j = tid >> 5, b = tid & 31;

    __shared__ float hs[HCHUNK * 32];
    __shared__ float ps[20][32];
    __shared__ float sa[60], ca[60];

    if (tid < 60) { float v = alphabet[tid]; sa[tid] = sinf(v); ca[tid] = cosf(v); }

    float acc = blin[j];
    const float* hb = g_h1 + (long)l * (H2 * BATCH);
    const float* w = wlin + j * H2;
    for (int k0 = 0; k0 < H2; k0 += HCHUNK) {
        __syncthreads();
#pragma unroll
        for (int i = 0; i < (HCHUNK * 32) / 640; i++)
            hs[tid + 640 * i] = hb[k0 * 32 + tid + 640 * i];
        __syncthreads();
#pragma unroll 8
        for (int k = 0; k < HCHUNK; k += 4) {
            float4 w4 = *(const float4*)(w + k0 + k);
            acc += w4.x * hs[(k + 0) * 32 + b];
            acc += w4.y * hs[(k + 1) * 32 + b];
            acc += w4.z * hs[(k + 2) * 32 + b];
            acc += w4.w * hs[(k + 3) * 32 + b];
        }
    }
    float m = acc;
#pragma unroll
    for (int o = 16; o; o >>= 1) m = fmaxf(m, __shfl_xor_sync(0xffffffffu, m, o));
    float e = expf(acc - m);
    float ssum = e;
#pragma unroll
    for (int o = 16; o; o >>= 1) ssum += __shfl_xor_sync(0xffffffffu, ssum, o);
    ps[j][b] = e / ssum;
    __syncthreads();

    if (tid < 96) {
        int b2 = tid / 3, i = tid - b2 * 3;
        float ssin = 0.f, scos = 0.f;
#pragma unroll
        for (int jj = 0; jj < 20; jj++) {
            float p = ps[jj][b2];
            ssin += p * sa[jj * 3 + i];
            scos += p * ca[jj * 3 + i];
        }
        g_ang[l * 96 + b2 * 3 + i] = atan2f(ssin, scos);
    }
}

// =============================================================================
// NeRF backbone extension (unchanged).
// =============================================================================
__global__ void nerf_kernel(float* __restrict__ out)
{
    int b = threadIdx.x;
    float ax = 0.f,   ay = 0.f,   az = 0.f;
    float bx = 100.f, by = 0.f,   bz = 0.f;
    float cx = 200.f, cy = 100.f, cz = 0.f;

    const float BL0 = 145.801f, BL1 = 152.326f, BL2 = 132.868f;
    const float TH0 = 2.124f,   TH1 = 1.941f,   TH2 = 2.028f;
    float d0a = -BL0 * cosf(TH0), d1a = BL0 * sinf(TH0);
    float d0b = -BL1 * cosf(TH1), d1b = BL1 * sinf(TH1);
    float d0c = -BL2 * cosf(TH2), d1c = BL2 * sinf(TH2);

    for (int s = 0; s < NCOORD; s++) {
        float phi = g_ang[s * 32 + b];
        int m = s - (s / 3) * 3;
        float d0 = (m == 0) ? d0a : (m == 1) ? d0b : d0c;
        float rs = (m == 0) ? d1a : (m == 1) ? d1b : d1c;

        float vx = cx - bx, vy = cy - by, vz = cz - bz;
        float inv = 1.f / (sqrtf(vx * vx + vy * vy + vz * vz) + 1e-12f);
        float bcx = vx * inv, bcy = vy * inv, bcz = vz * inv;

        float ux = bx - ax, uy = by - ay, uz = bz - az;
        float nx = uy * bcz - uz * bcy;
        float ny = uz * bcx - ux * bcz;
        float nz = ux * bcy - uy * bcx;
        float invn = 1.f / (sqrtf(nx * nx + ny * ny + nz * nz) + 1e-12f);
        nx *= invn; ny *= invn; nz *= invn;

        float mx = ny * bcz - nz * bcy;
        float my = nz * bcx - nx * bcz;
        float mz = nx * bcy - ny * bcx;

        float sp, cp;
        sincosf(phi, &sp, &cp);
        float d1 = rs * cp, d2 = rs * sp;

        float dx = cx + d0 * bcx + d1 * mx + d2 * nx;
        float dy = cy + d0 * bcy + d1 * my + d2 * ny;
        float dz = cz + d0 * bcz + d1 * mz + d2 * nz;

        out[s * 96 + b * 3 + 0] = dx;
        out[s * 96 + b * 3 + 1] = dy;
        out[s * 96 + b * 3 + 2] = dz;

        ax = bx; ay = by; az = bz;
        bx = cx; by = cy; bz = cz;
        cx = dx; cy = dy; cz = dz;
    }
}

// =============================================================================
extern "C" void kernel_launch(void* const* d_in, const int* in_sizes, int n_in,
                              void* d_out, int out_size)
{
    const float* x     = (const float*)d_in[0];
    const float* wih0  = (const float*)d_in[1];
    const float* whh0  = (const float*)d_in[2];
    const float* bih0  = (const float*)d_in[3];
    const float* bhh0  = (const float*)d_in[4];
    const float* wih1  = (const float*)d_in[5];
    const float* whh1  = (const float*)d_in[6];
    const float* bih1  = (const float*)d_in[7];
    const float* bhh1  = (const float*)d_in[8];
    const float* wlin  = (const float*)d_in[9];
    const float* blin  = (const float*)d_in[10];
    const float* alpha = (const float*)d_in[11];
    float* out = (float*)d_out;

    static int attr_done = 0;
    if (!attr_done) {
        cudaFuncSetAttribute(lstm_persist,
                             cudaFuncAttributeMaxDynamicSharedMemorySize, SMEM_LSTM);
        attr_done = 1;
    }

    dim3 gemm_grid(50, 175);   // N/128, M/128

    float* G0p; cudaGetSymbolAddress((void**)&G0p, g_G0);
    float* G1p; cudaGetSymbolAddress((void**)&G1p, g_G1);
    float* h0p; cudaGetSymbolAddress((void**)&h0p, g_h0);

    // Layer 0 input-side pre-activations: G0 = x @ Wih0^T + bih0 + bhh0
    gemm_gates<<<gemm_grid, 256>>>(x, wih0, bih0, bhh0, G0p, DIN, DIN, 0);

    // Layer 0 recurrence: single persistent launch (both directions)
    lstm_persist<<<100, 256, SMEM_LSTM>>>(whh0, 0);

    // Layer 1 input-side pre-activations: G1 = h0 @ Wih1^T + bih1 + bhh1
    gemm_gates<<<gemm_grid, 256>>>(h0p, wih1, bih1, bhh1, G1p, H2, H2, 1);

    // Layer 1 recurrence
    lstm_persist<<<100, 256, SMEM_LSTM>>>(whh1, 1);

    // Head: linear -> softmax(batch dim) -> angles
    head_kernel<<<LSEQ, 640>>>(wlin, blin, alpha);

    // NeRF extension -> output coords [2100][32][3]
    nerf_kernel<<<1, 32>>>(out);
}